// round 1
// baseline (speedup 1.0000x reference)
#include <cuda_runtime.h>

// ---------------------------------------------------------------------------
// Problem constants
// ---------------------------------------------------------------------------
namespace {
constexpr int kHeads = 12;
constexpr int kTok   = 197;               // N_PATCH + 1
constexpr int kDim   = 768;
constexpr int kHd    = 64;
constexpr int kBatch = 64;
constexpr int kM     = kBatch * kTok;     // 12608 (divisible by 64)
constexpr int kQkvN  = 3 * kDim;          // 2304
constexpr float kScale = 0.125f;          // hd^-0.5
}  // namespace

// Scratch (static device globals; no runtime allocation allowed)
__device__ float g_qkv[(size_t)kM * kQkvN];             // (B, N, 3, H, hd) = (B,N,2304)
__device__ float g_attn[(size_t)kM * kDim];             // (B, N, C) pre-projection
__device__ float g_rpb[(size_t)kHeads * kTok * kTok];   // (H, N, N)

// ---------------------------------------------------------------------------
// Relative position bias expansion: g_rpb[h][i][j] = table[idx[i][j]][h]
// ---------------------------------------------------------------------------
__global__ void rpb_expand(const int* __restrict__ idx, const float* __restrict__ tbl) {
  int t = blockIdx.x * blockDim.x + threadIdx.x;
  if (t >= kTok * kTok) return;
  int id = idx[t];
#pragma unroll
  for (int h = 0; h < kHeads; h++)
    g_rpb[(size_t)h * kTok * kTok + t] = tbl[id * kHeads + h];
}

// ---------------------------------------------------------------------------
// Tiled SGEMM:  C[m][n] = sum_k A[m][k] * W[n][k]  (+bias epilogue)
// BM=BN=64, BK=16, 256 threads, 4x4 register micro-tile.
// MODE 0: qkv epilogue (bias = [q_bias, 0, v_bias], q part scaled by 0.125)
// MODE 1: proj epilogue (bias = b0)
// M and N must be multiples of 64, K multiple of 16 (true for all our shapes).
// ---------------------------------------------------------------------------
template <int MODE>
__global__ __launch_bounds__(256)
void gemm_bias(const float* __restrict__ A, const float* __restrict__ W,
               float* __restrict__ C, int K, int N,
               const float* __restrict__ b0, const float* __restrict__ b1) {
  __shared__ float As[16][64];
  __shared__ float Bs[16][64];
  const int t  = threadIdx.x;
  const int tx = t & 15, ty = t >> 4;
  const int m0 = blockIdx.y * 64, n0 = blockIdx.x * 64;
  const int lr = t >> 2;          // 0..63: tile row
  const int lk = (t & 3) * 4;     // 0,4,8,12: k sub-offset
  const float* Ap = A + (size_t)(m0 + lr) * K + lk;
  const float* Wp = W + (size_t)(n0 + lr) * K + lk;

  float acc[4][4] = {};
  for (int k0 = 0; k0 < K; k0 += 16) {
    float4 a4 = *(const float4*)(Ap + k0);
    float4 b4 = *(const float4*)(Wp + k0);
    As[lk + 0][lr] = a4.x; As[lk + 1][lr] = a4.y;
    As[lk + 2][lr] = a4.z; As[lk + 3][lr] = a4.w;
    Bs[lk + 0][lr] = b4.x; Bs[lk + 1][lr] = b4.y;
    Bs[lk + 2][lr] = b4.z; Bs[lk + 3][lr] = b4.w;
    __syncthreads();
#pragma unroll
    for (int kk = 0; kk < 16; kk++) {
      float4 av = *(const float4*)&As[kk][ty * 4];
      float4 bv = *(const float4*)&Bs[kk][tx * 4];
      float a[4] = {av.x, av.y, av.z, av.w};
      float b[4] = {bv.x, bv.y, bv.z, bv.w};
#pragma unroll
      for (int r = 0; r < 4; r++)
#pragma unroll
        for (int c = 0; c < 4; c++) acc[r][c] = fmaf(a[r], b[c], acc[r][c]);
    }
    __syncthreads();
  }

#pragma unroll
  for (int r = 0; r < 4; r++) {
    int m = m0 + ty * 4 + r;
#pragma unroll
    for (int c = 0; c < 4; c++) {
      int n = n0 + tx * 4 + c;
      float v = acc[r][c];
      if (MODE == 0) {
        float bias = (n < kDim) ? b0[n] : ((n < 2 * kDim) ? 0.f : b1[n - 2 * kDim]);
        v += bias;
        if (n < kDim) v *= kScale;
      } else {
        v += b0[n];
      }
      C[(size_t)m * N + n] = v;
    }
  }
}

// ---------------------------------------------------------------------------
// Attention kernel. One block = one (b, h) pair x 32 query rows.
// Phase A: S[32 x 197] = Q_tile @ K^T      (K chunks of 128, SMEM outer product)
// Phase B: softmax(S + rpb) row-wise        (warp per 4 rows)
// Phase C: O[32 x 64]  = P @ V              (V chunks of 128)
// ---------------------------------------------------------------------------
namespace {
constexpr int TQ   = 32;
constexpr int KC   = 128;
constexpr int SSTR = 260;   // score row stride (covers 2*KC=256 cols + pad)
constexpr int QSTR = 36;    // Qs[d][i], stride 36 (16B-aligned float4 rows)
constexpr int KSTR = 132;   // Ks[d][j], stride 132
constexpr int VSTR = 68;    // Vs[j][d], stride 68
constexpr int kAttnSmemFloats = TQ * SSTR + 64 * QSTR + KC * VSTR;  // 8320+2304+8704
constexpr int kAttnSmemBytes  = kAttnSmemFloats * 4;                // 77312
}  // namespace

__global__ __launch_bounds__(256)
void attn_kernel() {
  extern __shared__ float sm[];
  float* S  = sm;                   // [TQ][SSTR]
  float* Qs = sm + TQ * SSTR;       // [64][QSTR]  (d-major, transposed Q)
  float* KV = Qs + 64 * QSTR;       // union: Ks [64][KSTR] / Vs [KC][VSTR]

  const int t    = threadIdx.x;
  const int tile = blockIdx.x;
  const int bh   = blockIdx.y;
  const int b    = bh / kHeads;
  const int h    = bh - b * kHeads;
  const int i0g  = tile * TQ;

  const float* Qb = g_qkv + (size_t)b * kTok * kQkvN + h * kHd;
  const float* Kb = Qb + kDim;
  const float* Vb = Qb + 2 * kDim;

  // ---- load Q tile transposed: Qs[d][i] ----
  {
    int i  = t >> 3;             // 0..31
    int d0 = (t & 7) * 8;        // 0..56
    int qi = i0g + i;
    float4 v0 = {0.f, 0.f, 0.f, 0.f}, v1 = {0.f, 0.f, 0.f, 0.f};
    if (qi < kTok) {
      const float* p = Qb + (size_t)qi * kQkvN + d0;
      v0 = *(const float4*)p;
      v1 = *(const float4*)(p + 4);
    }
    Qs[(d0 + 0) * QSTR + i] = v0.x; Qs[(d0 + 1) * QSTR + i] = v0.y;
    Qs[(d0 + 2) * QSTR + i] = v0.z; Qs[(d0 + 3) * QSTR + i] = v0.w;
    Qs[(d0 + 4) * QSTR + i] = v1.x; Qs[(d0 + 5) * QSTR + i] = v1.y;
    Qs[(d0 + 6) * QSTR + i] = v1.z; Qs[(d0 + 7) * QSTR + i] = v1.w;
  }
  __syncthreads();

  const int ti = t >> 5;   // warp id 0..7 -> 4 query rows
  const int tj = t & 31;   // lane

  // ---- Phase A: scores ----
  for (int c0 = 0; c0 < 2; c0++) {
    const int j0 = c0 * KC;
    {  // load K chunk transposed: Ks[d][j]
      int j  = t >> 1;
      int d0 = (t & 1) * 32;
      int kj = j0 + j;
      const float* p = Kb + (size_t)kj * kQkvN + d0;
#pragma unroll
      for (int q = 0; q < 8; q++) {
        float4 v = {0.f, 0.f, 0.f, 0.f};
        if (kj < kTok) v = *(const float4*)(p + q * 4);
        int d = d0 + q * 4;
        KV[(d + 0) * KSTR + j] = v.x;
        KV[(d + 1) * KSTR + j] = v.y;
        KV[(d + 2) * KSTR + j] = v.z;
        KV[(d + 3) * KSTR + j] = v.w;
      }
    }
    __syncthreads();

    float acc[4][4] = {};
#pragma unroll 16
    for (int d = 0; d < 64; d++) {
      float4 av = *(const float4*)&Qs[d * QSTR + ti * 4];
      float4 bv = *(const float4*)&KV[d * KSTR + tj * 4];
      float a[4] = {av.x, av.y, av.z, av.w};
      float bb[4] = {bv.x, bv.y, bv.z, bv.w};
#pragma unroll
      for (int r = 0; r < 4; r++)
#pragma unroll
        for (int c = 0; c < 4; c++) acc[r][c] = fmaf(a[r], bb[c], acc[r][c]);
    }
#pragma unroll
    for (int r = 0; r < 4; r++)
#pragma unroll
      for (int c = 0; c < 4; c++)
        S[(ti * 4 + r) * SSTR + j0 + tj * 4 + c] = acc[r][c];
    __syncthreads();
  }

  // ---- Phase B: softmax(S + rpb), rows are warp-private ----
  {
    const int lane = tj;
#pragma unroll
    for (int r = 0; r < 4; r++) {
      int i  = ti * 4 + r;
      int qi = min(i0g + i, kTok - 1);
      const float* rp = g_rpb + ((size_t)h * kTok + qi) * kTok;
      float vals[7];
      float mx = -1e30f;
#pragma unroll
      for (int k = 0; k < 7; k++) {
        int j = lane + k * 32;
        float v = -1e30f;
        if (j < kTok) v = S[i * SSTR + j] + rp[j];
        vals[k] = v;
        mx = fmaxf(mx, v);
      }
#pragma unroll
      for (int o = 16; o; o >>= 1) mx = fmaxf(mx, __shfl_xor_sync(0xffffffffu, mx, o));
      float sum = 0.f;
#pragma unroll
      for (int k = 0; k < 7; k++) {
        int j = lane + k * 32;
        float e = (j < kTok) ? __expf(vals[k] - mx) : 0.f;
        vals[k] = e;
        sum += e;
      }
#pragma unroll
      for (int o = 16; o; o >>= 1) sum += __shfl_xor_sync(0xffffffffu, sum, o);
      float inv = 1.f / sum;
#pragma unroll
      for (int k = 0; k < 7; k++) {
        int j = lane + k * 32;
        S[i * SSTR + j] = (j < kTok) ? vals[k] * inv : 0.f;
      }
      S[i * SSTR + 224 + lane] = 0.f;  // zero padding up to 256
    }
  }
  __syncthreads();

  // ---- Phase C: O = P @ V ----
  float accO[4][2] = {};
  for (int c0 = 0; c0 < 2; c0++) {
    const int j0 = c0 * KC;
    {  // load V chunk natural: Vs[j][d]
      int j  = t >> 1;
      int d0 = (t & 1) * 32;
      int vj = j0 + j;
      const float* p = Vb + (size_t)vj * kQkvN + d0;
#pragma unroll
      for (int q = 0; q < 8; q++) {
        float4 v = {0.f, 0.f, 0.f, 0.f};
        if (vj < kTok) v = *(const float4*)(p + q * 4);
        *(float4*)&KV[j * VSTR + d0 + q * 4] = v;
      }
    }
    __syncthreads();
#pragma unroll 16
    for (int jj = 0; jj < KC; jj++) {
      float p0 = S[(ti * 4 + 0) * SSTR + j0 + jj];
      float p1 = S[(ti * 4 + 1) * SSTR + j0 + jj];
      float p2 = S[(ti * 4 + 2) * SSTR + j0 + jj];
      float p3 = S[(ti * 4 + 3) * SSTR + j0 + jj];
      float2 bv = *(const float2*)&KV[jj * VSTR + tj * 2];
      accO[0][0] = fmaf(p0, bv.x, accO[0][0]); accO[0][1] = fmaf(p0, bv.y, accO[0][1]);
      accO[1][0] = fmaf(p1, bv.x, accO[1][0]); accO[1][1] = fmaf(p1, bv.y, accO[1][1]);
      accO[2][0] = fmaf(p2, bv.x, accO[2][0]); accO[2][1] = fmaf(p2, bv.y, accO[2][1]);
      accO[3][0] = fmaf(p3, bv.x, accO[3][0]); accO[3][1] = fmaf(p3, bv.y, accO[3][1]);
    }
    __syncthreads();
  }

#pragma unroll
  for (int r = 0; r < 4; r++) {
    int qi = i0g + ti * 4 + r;
    if (qi < kTok) {
      float* o = g_attn + ((size_t)b * kTok + qi) * kDim + h * kHd + tj * 2;
      o[0] = accO[r][0];
      o[1] = accO[r][1];
    }
  }
}

// ---------------------------------------------------------------------------
// Launch
// ---------------------------------------------------------------------------
extern "C" void kernel_launch(void* const* d_in, const int* in_sizes, int n_in,
                              void* d_out, int out_size) {
  const float* x         = (const float*)d_in[0];
  const float* qkv_w     = (const float*)d_in[1];
  const float* q_bias    = (const float*)d_in[2];
  const float* v_bias    = (const float*)d_in[3];
  const float* rpb_table = (const float*)d_in[4];
  const float* proj_w    = (const float*)d_in[5];
  const float* proj_b    = (const float*)d_in[6];
  const int*   rel_idx   = (const int*)d_in[7];
  float* out = (float*)d_out;

  float *qkv_ptr = nullptr, *attn_ptr = nullptr;
  cudaGetSymbolAddress((void**)&qkv_ptr, g_qkv);
  cudaGetSymbolAddress((void**)&attn_ptr, g_attn);

  // (1) relative position bias expansion
  rpb_expand<<<(kTok * kTok + 255) / 256, 256>>>(rel_idx, rpb_table);

  // (2) QKV projection: (12608 x 768) @ (2304 x 768)^T + bias, q scaled
  gemm_bias<0><<<dim3(kQkvN / 64, kM / 64), 256>>>(x, qkv_w, qkv_ptr, kDim, kQkvN,
                                                   q_bias, v_bias);

  // (3) attention
  cudaFuncSetAttribute(attn_kernel, cudaFuncAttributeMaxDynamicSharedMemorySize,
                       kAttnSmemBytes);
  attn_kernel<<<dim3(7, kBatch * kHeads), 256, kAttnSmemBytes>>>();

  // (4) output projection: (12608 x 768) @ (768 x 768)^T + proj_b
  gemm_bias<1><<<dim3(kDim / 64, kM / 64), 256>>>(attn_ptr, proj_w, out, kDim, kDim,
                                                  proj_b, nullptr);
}

// round 2
// speedup vs baseline: 1.9403x; 1.9403x over previous
#include <cuda_runtime.h>
#include <cstdint>

// ---------------------------------------------------------------------------
// Problem constants
// ---------------------------------------------------------------------------
namespace {
constexpr int kHeads = 12;
constexpr int kTok   = 197;               // N_PATCH + 1
constexpr int kDim   = 768;
constexpr int kBatch = 64;
constexpr int kM     = kBatch * kTok;     // 12608
constexpr int kQkvN  = 3 * kDim;          // 2304
constexpr float kScale = 0.125f;          // hd^-0.5
}  // namespace

// Scratch (static device globals; no runtime allocation allowed)
__device__ float g_qkv[(size_t)kM * kQkvN];             // (B, N, 3C)
__device__ float g_attn[(size_t)kM * kDim];             // (B, N, C) pre-projection
__device__ float g_rpb[(size_t)kHeads * kTok * kTok];   // (H, N, N)

// ---------------------------------------------------------------------------
// Relative position bias expansion: g_rpb[h][i][j] = table[idx[i][j]][h]
// ---------------------------------------------------------------------------
__global__ void rpb_expand(const int* __restrict__ idx, const float* __restrict__ tbl) {
  int t = blockIdx.x * blockDim.x + threadIdx.x;
  if (t >= kTok * kTok) return;
  int id = idx[t];
#pragma unroll
  for (int h = 0; h < kHeads; h++)
    g_rpb[(size_t)h * kTok * kTok + t] = tbl[id * kHeads + h];
}

// ---------------------------------------------------------------------------
// TF32 tensor-core GEMM:  C[m][n] = sum_k A[m][k] * W[n][k]  (+bias epilogue)
// Block tile 128x128x16, 256 threads = 8 warps (2x4), warp tile 64x32.
// mma.sync.aligned.m16n8k8.row.col.f32.tf32.tf32.f32
// SMEM holds tiles pre-permuted into fragment order + XOR swizzle:
//   A: [kstep(2)][mtile(8)][lane(32)][reg(4)]  (512B per 16x8 tile, LDS.128 read)
//   B: [kstep(2)][ntile(16)][lane(32)][reg(2)] (256B per 8x8 tile, LDS.64 read)
// MODE 0: qkv epilogue (bias = [q_bias, 0, v_bias], q part scaled by 0.125)
// MODE 1: proj epilogue (bias = b0)
// ---------------------------------------------------------------------------
__device__ __forceinline__ float tf32_rna(float x) {
  uint32_t r;
  asm("cvt.rna.tf32.f32 %0, %1;" : "=r"(r) : "f"(x));
  return __uint_as_float(r);
}

__device__ __forceinline__ void mma_tf32(float (&d)[4], const float4& a, const float2& b) {
  uint32_t a0 = __float_as_uint(a.x), a1 = __float_as_uint(a.y);
  uint32_t a2 = __float_as_uint(a.z), a3 = __float_as_uint(a.w);
  uint32_t b0 = __float_as_uint(b.x), b1 = __float_as_uint(b.y);
  asm volatile(
      "mma.sync.aligned.m16n8k8.row.col.f32.tf32.tf32.f32 "
      "{%0,%1,%2,%3}, {%4,%5,%6,%7}, {%8,%9}, {%0,%1,%2,%3};"
      : "+f"(d[0]), "+f"(d[1]), "+f"(d[2]), "+f"(d[3])
      : "r"(a0), "r"(a1), "r"(a2), "r"(a3), "r"(b0), "r"(b1));
}

template <int MODE>
__global__ __launch_bounds__(256)
void gemm_tf32(const float* __restrict__ A, const float* __restrict__ W,
               float* __restrict__ C, int M, int K, int N,
               const float* __restrict__ b0, const float* __restrict__ b1) {
  __shared__ float As[2][2048];  // 2 ksteps * 8 mtiles * 32 lanes * 4 regs
  __shared__ float Bs[2][2048];  // 2 ksteps * 16 ntiles * 32 lanes * 2 regs

  const int t    = threadIdx.x;
  const int lane = t & 31;
  const int wid  = t >> 5;
  const int wm   = (wid >> 2) * 64;  // warp m offset: 0 or 64
  const int wn   = (wid & 3) * 32;   // warp n offset: 0,32,64,96
  const int m0   = blockIdx.y * 128;
  const int n0   = blockIdx.x * 128;

  // loader decomposition: 512 float4 per tile per matrix; 2 per thread
  const int lrow0 = t >> 1;               // not used; keep simple per-i below
  (void)lrow0;

  float4 pa[2], pb[2];

  auto load_global = [&](int kb) {
#pragma unroll
    for (int i = 0; i < 2; i++) {
      int idx = t + i * 256;
      int row = idx >> 2;      // 0..127
      int kc  = idx & 3;       // 0..3 (float4 within 16-k)
      int mg  = m0 + row;
      if (mg < M)
        pa[i] = *(const float4*)(A + (size_t)mg * K + kb + kc * 4);
      else
        pa[i] = make_float4(0.f, 0.f, 0.f, 0.f);
      int ng = n0 + row;
      pb[i] = *(const float4*)(W + (size_t)ng * K + kb + kc * 4);
    }
  };

  auto store_smem = [&](int buf) {
#pragma unroll
    for (int i = 0; i < 2; i++) {
      int idx = t + i * 256;
      int row = idx >> 2;
      int kc  = idx & 3;
      int kstep = kc >> 1;
      int regk  = (kc & 1) * 2;  // k-part of reg (A), reg (B)
      // ---- A ----
      {
        int mt  = row >> 4;
        int r7  = row & 7;
        int rb3 = (row >> 3) & 1;
        int sw  = (r7 >> 1) & 3;
        float v[4] = {pa[i].x, pa[i].y, pa[i].z, pa[i].w};
#pragma unroll
        for (int j = 0; j < 4; j++) {
          int lp = (r7 * 4 + j) ^ sw;
          As[buf][((kstep * 8 + mt) * 32 + lp) * 4 + rb3 + regk] = tf32_rna(v[j]);
        }
      }
      // ---- B ----
      {
        int nt = row >> 3;
        int c  = row & 7;
        int sw = (c >> 2) & 1;
        float v[4] = {pb[i].x, pb[i].y, pb[i].z, pb[i].w};
#pragma unroll
        for (int j = 0; j < 4; j++) {
          int lp = (c * 4 + j) ^ sw;
          Bs[buf][((kstep * 16 + nt) * 32 + lp) * 2 + (kc & 1)] = tf32_rna(v[j]);
        }
      }
    }
  };

  float acc[4][4][4] = {};

  const int nkb = K / 16;
  load_global(0);
  store_smem(0);
  __syncthreads();

  int buf = 0;
  const int unitA = lane ^ ((lane >> 3) & 3);
  const int unitB = lane ^ ((lane >> 4) & 1);
  const int mtb   = wm >> 4;  // 0 or 4
  const int ntb   = wn >> 3;  // 0,4,8,12

  for (int kb = 0; kb < nkb; kb++) {
    bool has_next = (kb + 1 < nkb);
    if (has_next) load_global((kb + 1) * 16);

#pragma unroll
    for (int ks = 0; ks < 2; ks++) {
      float4 af[4];
      float2 bf[4];
#pragma unroll
      for (int mt = 0; mt < 4; mt++)
        af[mt] = *(const float4*)&As[buf][((ks * 8 + mtb + mt) * 32 + unitA) * 4];
#pragma unroll
      for (int nt = 0; nt < 4; nt++)
        bf[nt] = *(const float2*)&Bs[buf][((ks * 16 + ntb + nt) * 32 + unitB) * 2];
#pragma unroll
      for (int mt = 0; mt < 4; mt++)
#pragma unroll
        for (int nt = 0; nt < 4; nt++)
          mma_tf32(acc[mt][nt], af[mt], bf[nt]);
    }

    if (has_next) {
      store_smem(buf ^ 1);
      __syncthreads();
      buf ^= 1;
    }
  }

  // ---- epilogue ----
  const int mrow = (lane >> 2);
  const int ncol = (lane & 3) * 2;
#pragma unroll
  for (int mt = 0; mt < 4; mt++) {
#pragma unroll
    for (int half = 0; half < 2; half++) {
      int m = m0 + wm + mt * 16 + mrow + half * 8;
      if (m >= M) continue;
#pragma unroll
      for (int nt = 0; nt < 4; nt++) {
        int n = n0 + wn + nt * 8 + ncol;
        float v0 = acc[mt][nt][half * 2 + 0];
        float v1 = acc[mt][nt][half * 2 + 1];
        if (MODE == 0) {
          float bias0 = (n < kDim) ? b0[n] : ((n < 2 * kDim) ? 0.f : b1[n - 2 * kDim]);
          float bias1 = (n + 1 < kDim) ? b0[n + 1]
                        : ((n + 1 < 2 * kDim) ? 0.f : b1[n + 1 - 2 * kDim]);
          v0 += bias0;
          v1 += bias1;
          if (n < kDim) { v0 *= kScale; v1 *= kScale; }
        } else {
          v0 += b0[n];
          v1 += b0[n + 1];
        }
        *(float2*)(C + (size_t)m * N + n) = make_float2(v0, v1);
      }
    }
  }
}

// ---------------------------------------------------------------------------
// Attention kernel (unchanged from R1). One block = one (b, h) x 32 query rows.
// ---------------------------------------------------------------------------
namespace {
constexpr int TQ   = 32;
constexpr int KC   = 128;
constexpr int SSTR = 260;
constexpr int QSTR = 36;
constexpr int KSTR = 132;
constexpr int VSTR = 68;
constexpr int kAttnSmemFloats = TQ * SSTR + 64 * QSTR + KC * VSTR;
constexpr int kAttnSmemBytes  = kAttnSmemFloats * 4;  // 77312
}  // namespace

__global__ __launch_bounds__(256)
void attn_kernel() {
  extern __shared__ float sm[];
  float* S  = sm;
  float* Qs = sm + TQ * SSTR;
  float* KV = Qs + 64 * QSTR;

  const int t    = threadIdx.x;
  const int tile = blockIdx.x;
  const int bh   = blockIdx.y;
  const int b    = bh / kHeads;
  const int h    = bh - b * kHeads;
  const int i0g  = tile * TQ;

  const float* Qb = g_qkv + (size_t)b * kTok * kQkvN + h * 64;
  const float* Kb = Qb + kDim;
  const float* Vb = Qb + 2 * kDim;

  {
    int i  = t >> 3;
    int d0 = (t & 7) * 8;
    int qi = i0g + i;
    float4 v0 = {0.f, 0.f, 0.f, 0.f}, v1 = {0.f, 0.f, 0.f, 0.f};
    if (qi < kTok) {
      const float* p = Qb + (size_t)qi * kQkvN + d0;
      v0 = *(const float4*)p;
      v1 = *(const float4*)(p + 4);
    }
    Qs[(d0 + 0) * QSTR + i] = v0.x; Qs[(d0 + 1) * QSTR + i] = v0.y;
    Qs[(d0 + 2) * QSTR + i] = v0.z; Qs[(d0 + 3) * QSTR + i] = v0.w;
    Qs[(d0 + 4) * QSTR + i] = v1.x; Qs[(d0 + 5) * QSTR + i] = v1.y;
    Qs[(d0 + 6) * QSTR + i] = v1.z; Qs[(d0 + 7) * QSTR + i] = v1.w;
  }
  __syncthreads();

  const int ti = t >> 5;
  const int tj = t & 31;

  for (int c0 = 0; c0 < 2; c0++) {
    const int j0 = c0 * KC;
    {
      int j  = t >> 1;
      int d0 = (t & 1) * 32;
      int kj = j0 + j;
      const float* p = Kb + (size_t)kj * kQkvN + d0;
#pragma unroll
      for (int q = 0; q < 8; q++) {
        float4 v = {0.f, 0.f, 0.f, 0.f};
        if (kj < kTok) v = *(const float4*)(p + q * 4);
        int d = d0 + q * 4;
        KV[(d + 0) * KSTR + j] = v.x;
        KV[(d + 1) * KSTR + j] = v.y;
        KV[(d + 2) * KSTR + j] = v.z;
        KV[(d + 3) * KSTR + j] = v.w;
      }
    }
    __syncthreads();

    float acc[4][4] = {};
#pragma unroll 16
    for (int d = 0; d < 64; d++) {
      float4 av = *(const float4*)&Qs[d * QSTR + ti * 4];
      float4 bv = *(const float4*)&KV[d * KSTR + tj * 4];
      float a[4] = {av.x, av.y, av.z, av.w};
      float bb[4] = {bv.x, bv.y, bv.z, bv.w};
#pragma unroll
      for (int r = 0; r < 4; r++)
#pragma unroll
        for (int c = 0; c < 4; c++) acc[r][c] = fmaf(a[r], bb[c], acc[r][c]);
    }
#pragma unroll
    for (int r = 0; r < 4; r++)
#pragma unroll
      for (int c = 0; c < 4; c++)
        S[(ti * 4 + r) * SSTR + j0 + tj * 4 + c] = acc[r][c];
    __syncthreads();
  }

  {
    const int lane = tj;
#pragma unroll
    for (int r = 0; r < 4; r++) {
      int i  = ti * 4 + r;
      int qi = min(i0g + i, kTok - 1);
      const float* rp = g_rpb + ((size_t)h * kTok + qi) * kTok;
      float vals[7];
      float mx = -1e30f;
#pragma unroll
      for (int k = 0; k < 7; k++) {
        int j = lane + k * 32;
        float v = -1e30f;
        if (j < kTok) v = S[i * SSTR + j] + rp[j];
        vals[k] = v;
        mx = fmaxf(mx, v);
      }
#pragma unroll
      for (int o = 16; o; o >>= 1) mx = fmaxf(mx, __shfl_xor_sync(0xffffffffu, mx, o));
      float sum = 0.f;
#pragma unroll
      for (int k = 0; k < 7; k++) {
        int j = lane + k * 32;
        float e = (j < kTok) ? __expf(vals[k] - mx) : 0.f;
        vals[k] = e;
        sum += e;
      }
#pragma unroll
      for (int o = 16; o; o >>= 1) sum += __shfl_xor_sync(0xffffffffu, sum, o);
      float inv = 1.f / sum;
#pragma unroll
      for (int k = 0; k < 7; k++) {
        int j = lane + k * 32;
        S[i * SSTR + j] = (j < kTok) ? vals[k] * inv : 0.f;
      }
      S[i * SSTR + 224 + lane] = 0.f;
    }
  }
  __syncthreads();

  float accO[4][2] = {};
  for (int c0 = 0; c0 < 2; c0++) {
    const int j0 = c0 * KC;
    {
      int j  = t >> 1;
      int d0 = (t & 1) * 32;
      int vj = j0 + j;
      const float* p = Vb + (size_t)vj * kQkvN + d0;
#pragma unroll
      for (int q = 0; q < 8; q++) {
        float4 v = {0.f, 0.f, 0.f, 0.f};
        if (vj < kTok) v = *(const float4*)(p + q * 4);
        *(float4*)&KV[j * VSTR + d0 + q * 4] = v;
      }
    }
    __syncthreads();
#pragma unroll 16
    for (int jj = 0; jj < KC; jj++) {
      float p0 = S[(ti * 4 + 0) * SSTR + j0 + jj];
      float p1 = S[(ti * 4 + 1) * SSTR + j0 + jj];
      float p2 = S[(ti * 4 + 2) * SSTR + j0 + jj];
      float p3 = S[(ti * 4 + 3) * SSTR + j0 + jj];
      float2 bv = *(const float2*)&KV[jj * VSTR + tj * 2];
      accO[0][0] = fmaf(p0, bv.x, accO[0][0]); accO[0][1] = fmaf(p0, bv.y, accO[0][1]);
      accO[1][0] = fmaf(p1, bv.x, accO[1][0]); accO[1][1] = fmaf(p1, bv.y, accO[1][1]);
      accO[2][0] = fmaf(p2, bv.x, accO[2][0]); accO[2][1] = fmaf(p2, bv.y, accO[2][1]);
      accO[3][0] = fmaf(p3, bv.x, accO[3][0]); accO[3][1] = fmaf(p3, bv.y, accO[3][1]);
    }
    __syncthreads();
  }

#pragma unroll
  for (int r = 0; r < 4; r++) {
    int qi = i0g + ti * 4 + r;
    if (qi < kTok) {
      float* o = g_attn + ((size_t)b * kTok + qi) * kDim + h * 64 + tj * 2;
      o[0] = accO[r][0];
      o[1] = accO[r][1];
    }
  }
}

// ---------------------------------------------------------------------------
// Launch
// ---------------------------------------------------------------------------
extern "C" void kernel_launch(void* const* d_in, const int* in_sizes, int n_in,
                              void* d_out, int out_size) {
  const float* x         = (const float*)d_in[0];
  const float* qkv_w     = (const float*)d_in[1];
  const float* q_bias    = (const float*)d_in[2];
  const float* v_bias    = (const float*)d_in[3];
  const float* rpb_table = (const float*)d_in[4];
  const float* proj_w    = (const float*)d_in[5];
  const float* proj_b    = (const float*)d_in[6];
  const int*   rel_idx   = (const int*)d_in[7];
  float* out = (float*)d_out;

  float *qkv_ptr = nullptr, *attn_ptr = nullptr;
  cudaGetSymbolAddress((void**)&qkv_ptr, g_qkv);
  cudaGetSymbolAddress((void**)&attn_ptr, g_attn);

  // (1) relative position bias expansion
  rpb_expand<<<(kTok * kTok + 255) / 256, 256>>>(rel_idx, rpb_table);

  // (2) QKV projection: (12608 x 768) @ (2304 x 768)^T + bias, q scaled
  {
    dim3 grid(kQkvN / 128, (kM + 127) / 128);
    gemm_tf32<0><<<grid, 256>>>(x, qkv_w, qkv_ptr, kM, kDim, kQkvN, q_bias, v_bias);
  }

  // (3) attention
  cudaFuncSetAttribute(attn_kernel, cudaFuncAttributeMaxDynamicSharedMemorySize,
                       kAttnSmemBytes);
  attn_kernel<<<dim3(7, kBatch * kHeads), 256, kAttnSmemBytes>>>();

  // (4) output projection: (12608 x 768) @ (768 x 768)^T + proj_b
  {
    dim3 grid(kDim / 128, (kM + 127) / 128);
    gemm_tf32<1><<<grid, 256>>>(attn_ptr, proj_w, out, kM, kDim, kDim, proj_b, nullptr);
  }
}

// round 3
// speedup vs baseline: 2.1801x; 1.1236x over previous
#include <cuda_runtime.h>
#include <cstdint>

// ---------------------------------------------------------------------------
// Problem constants
// ---------------------------------------------------------------------------
namespace {
constexpr int kHeads = 12;
constexpr int kTok   = 197;               // N_PATCH + 1
constexpr int kDim   = 768;
constexpr int kBatch = 64;
constexpr int kM     = kBatch * kTok;     // 12608
constexpr int kQkvN  = 3 * kDim;          // 2304
constexpr float kScale = 0.125f;          // hd^-0.5
}  // namespace

// Scratch (static device globals; no runtime allocation allowed)
__device__ float g_qkv[(size_t)kM * kQkvN];             // (B, N, 3C) fp32
__device__ float g_attn[(size_t)kM * kDim];             // (B, N, C), tf32-rounded
__device__ float g_rpb[(size_t)kHeads * kTok * kTok];   // (H, N, N)
__device__ float g_x[(size_t)kM * kDim];                // tf32-rounded x
__device__ float g_wqkv[(size_t)kQkvN * kDim];          // tf32-rounded qkv_w
__device__ float g_wproj[(size_t)kDim * kDim];          // tf32-rounded proj_w

__device__ __forceinline__ float tf32_rna(float x) {
  uint32_t r;
  asm("cvt.rna.tf32.f32 %0, %1;" : "=r"(r) : "f"(x));
  return __uint_as_float(r);
}

// ---------------------------------------------------------------------------
// Elementwise tf32 rounding (n divisible by 4)
// ---------------------------------------------------------------------------
__global__ void tf32_round_kernel(const float* __restrict__ in, float* __restrict__ out,
                                  int n4) {
  int i = blockIdx.x * blockDim.x + threadIdx.x;
  if (i >= n4) return;
  float4 v = ((const float4*)in)[i];
  v.x = tf32_rna(v.x); v.y = tf32_rna(v.y);
  v.z = tf32_rna(v.z); v.w = tf32_rna(v.w);
  ((float4*)out)[i] = v;
}

// ---------------------------------------------------------------------------
// Relative position bias expansion: g_rpb[h][i][j] = table[idx[i][j]][h]
// ---------------------------------------------------------------------------
__global__ void rpb_expand(const int* __restrict__ idx, const float* __restrict__ tbl) {
  int t = blockIdx.x * blockDim.x + threadIdx.x;
  if (t >= kTok * kTok) return;
  int id = idx[t];
#pragma unroll
  for (int h = 0; h < kHeads; h++)
    g_rpb[(size_t)h * kTok * kTok + t] = tbl[id * kHeads + h];
}

// ---------------------------------------------------------------------------
// TF32 tensor-core GEMM, cp.async 4-stage pipeline.
//   C[m][n] = sum_k A[m][k] * W[n][k]  (+bias epilogue)
// Inputs must already be tf32-rounded. Block tile 128x128x16, 8 warps, warp
// tile 64x32, mma.sync.m16n8k8. SMEM tiles row-major with stride 20 (pad) —
// fragment gathers (lane/4)*20 + lane%4 are bank-conflict-free.
// MODE 0: qkv epilogue (bias = [q_bias, 0, v_bias], q part scaled by 0.125)
// MODE 1: proj epilogue (bias = b0)
// N must be a multiple of 128; M tail handled by cp.async zero-fill + guards.
// ---------------------------------------------------------------------------
namespace {
constexpr int kStages      = 4;
constexpr int kSmStride    = 20;                     // floats per 16-k row
constexpr int kStageFloats = 2 * 128 * kSmStride;    // A + B per stage = 5120
constexpr int kGemmSmemBytes = kStages * kStageFloats * 4;  // 81920
}  // namespace

__device__ __forceinline__ void cp_async16(uint32_t dst, const void* src, bool pred) {
  int sz = pred ? 16 : 0;
  asm volatile("cp.async.ca.shared.global [%0], [%1], 16, %2;"
               :: "r"(dst), "l"(src), "r"(sz));
}
__device__ __forceinline__ void cp_commit() {
  asm volatile("cp.async.commit_group;");
}
__device__ __forceinline__ void cp_wait2() {
  asm volatile("cp.async.wait_group 2;");
}

__device__ __forceinline__ void mma_tf32(float (&d)[4], const float* a, const float* b) {
  uint32_t a0 = __float_as_uint(a[0]), a1 = __float_as_uint(a[1]);
  uint32_t a2 = __float_as_uint(a[2]), a3 = __float_as_uint(a[3]);
  uint32_t b0 = __float_as_uint(b[0]), b1 = __float_as_uint(b[1]);
  asm volatile(
      "mma.sync.aligned.m16n8k8.row.col.f32.tf32.tf32.f32 "
      "{%0,%1,%2,%3}, {%4,%5,%6,%7}, {%8,%9}, {%0,%1,%2,%3};"
      : "+f"(d[0]), "+f"(d[1]), "+f"(d[2]), "+f"(d[3])
      : "r"(a0), "r"(a1), "r"(a2), "r"(a3), "r"(b0), "r"(b1));
}

template <int MODE>
__global__ __launch_bounds__(256)
void gemm_tf32_pipe(const float* __restrict__ A, const float* __restrict__ W,
                    float* __restrict__ C, int M, int K, int N,
                    const float* __restrict__ b0, const float* __restrict__ b1) {
  extern __shared__ float sm[];

  const int t    = threadIdx.x;
  const int lane = t & 31;
  const int wid  = t >> 5;
  const int wm   = (wid >> 2) * 64;  // 0 or 64
  const int wn   = (wid & 3) * 32;   // 0,32,64,96
  const int m0   = blockIdx.y * 128;
  const int n0   = blockIdx.x * 128;

  const uint32_t smem_base = (uint32_t)__cvta_generic_to_shared(sm);

  // loader: 512 float4 per matrix per stage; 2 A + 2 B per thread
  const int lrow = t >> 1;          // for i-loop decomposition below
  (void)lrow;

  auto issue_stage = [&](int kb_idx) {
    int kb = kb_idx * 16;
    float* stA = sm + (kb_idx & 3) * kStageFloats;
    float* stB = stA + 128 * kSmStride;
    uint32_t uA = smem_base + (uint32_t)((kb_idx & 3) * kStageFloats) * 4;
    uint32_t uB = uA + 128 * kSmStride * 4;
#pragma unroll
    for (int i = 0; i < 2; i++) {
      int idx = t + i * 256;
      int row = idx >> 2;        // 0..127
      int c4  = (idx & 3) * 4;   // 0,4,8,12
      uint32_t soff = (uint32_t)(row * kSmStride + c4) * 4;
      int mg = m0 + row;
      cp_async16(uA + soff, A + (size_t)mg * K + kb + c4, mg < M);
      int ng = n0 + row;
      cp_async16(uB + soff, W + (size_t)ng * K + kb + c4, true);
    }
    (void)stA; (void)stB;
  };

  const int nkb = K / 16;
  // prologue: stages 0..2
#pragma unroll
  for (int s = 0; s < kStages - 1; s++) {
    issue_stage(s);
    cp_commit();
  }

  float acc[4][4][4] = {};
  const int lm = lane >> 2;
  const int lk = lane & 3;

  for (int kb = 0; kb < nkb; kb++) {
    cp_wait2();
    __syncthreads();

    if (kb + kStages - 1 < nkb) issue_stage(kb + kStages - 1);
    cp_commit();

    const float* As = sm + (kb & 3) * kStageFloats;
    const float* Bs = As + 128 * kSmStride;

#pragma unroll
    for (int ks = 0; ks < 2; ks++) {
      float af[4][4];
      float bf[4][2];
#pragma unroll
      for (int mt = 0; mt < 4; mt++) {
        int r = wm + mt * 16 + lm;
        int c = ks * 8 + lk;
        af[mt][0] = As[r * kSmStride + c];
        af[mt][1] = As[(r + 8) * kSmStride + c];
        af[mt][2] = As[r * kSmStride + c + 4];
        af[mt][3] = As[(r + 8) * kSmStride + c + 4];
      }
#pragma unroll
      for (int nt = 0; nt < 4; nt++) {
        int r = wn + nt * 8 + lm;
        int c = ks * 8 + lk;
        bf[nt][0] = Bs[r * kSmStride + c];
        bf[nt][1] = Bs[r * kSmStride + c + 4];
      }
#pragma unroll
      for (int mt = 0; mt < 4; mt++)
#pragma unroll
        for (int nt = 0; nt < 4; nt++)
          mma_tf32(acc[mt][nt], af[mt], bf[nt]);
    }
  }

  // ---- epilogue ----
  const int mrow = lane >> 2;
  const int ncol = (lane & 3) * 2;
#pragma unroll
  for (int mt = 0; mt < 4; mt++) {
#pragma unroll
    for (int half = 0; half < 2; half++) {
      int m = m0 + wm + mt * 16 + mrow + half * 8;
      if (m >= M) continue;
#pragma unroll
      for (int nt = 0; nt < 4; nt++) {
        int n = n0 + wn + nt * 8 + ncol;
        float v0 = acc[mt][nt][half * 2 + 0];
        float v1 = acc[mt][nt][half * 2 + 1];
        if (MODE == 0) {
          float bias0 = (n < kDim) ? b0[n] : ((n < 2 * kDim) ? 0.f : b1[n - 2 * kDim]);
          float bias1 = (n + 1 < kDim) ? b0[n + 1]
                        : ((n + 1 < 2 * kDim) ? 0.f : b1[n + 1 - 2 * kDim]);
          v0 += bias0;
          v1 += bias1;
          if (n < kDim) { v0 *= kScale; v1 *= kScale; }
        } else {
          v0 += b0[n];
          v1 += b0[n + 1];
        }
        *(float2*)(C + (size_t)m * N + n) = make_float2(v0, v1);
      }
    }
  }
}

// ---------------------------------------------------------------------------
// Attention kernel (as R2) — output is tf32-rounded for the proj GEMM.
// ---------------------------------------------------------------------------
namespace {
constexpr int TQ   = 32;
constexpr int KC   = 128;
constexpr int SSTR = 260;
constexpr int QSTR = 36;
constexpr int KSTR = 132;
constexpr int VSTR = 68;
constexpr int kAttnSmemFloats = TQ * SSTR + 64 * QSTR + KC * VSTR;
constexpr int kAttnSmemBytes  = kAttnSmemFloats * 4;  // 77312
}  // namespace

__global__ __launch_bounds__(256)
void attn_kernel() {
  extern __shared__ float smA[];
  float* S  = smA;
  float* Qs = smA + TQ * SSTR;
  float* KV = Qs + 64 * QSTR;

  const int t    = threadIdx.x;
  const int tile = blockIdx.x;
  const int bh   = blockIdx.y;
  const int b    = bh / kHeads;
  const int h    = bh - b * kHeads;
  const int i0g  = tile * TQ;

  const float* Qb = g_qkv + (size_t)b * kTok * kQkvN + h * 64;
  const float* Kb = Qb + kDim;
  const float* Vb = Qb + 2 * kDim;

  {
    int i  = t >> 3;
    int d0 = (t & 7) * 8;
    int qi = i0g + i;
    float4 v0 = {0.f, 0.f, 0.f, 0.f}, v1 = {0.f, 0.f, 0.f, 0.f};
    if (qi < kTok) {
      const float* p = Qb + (size_t)qi * kQkvN + d0;
      v0 = *(const float4*)p;
      v1 = *(const float4*)(p + 4);
    }
    Qs[(d0 + 0) * QSTR + i] = v0.x; Qs[(d0 + 1) * QSTR + i] = v0.y;
    Qs[(d0 + 2) * QSTR + i] = v0.z; Qs[(d0 + 3) * QSTR + i] = v0.w;
    Qs[(d0 + 4) * QSTR + i] = v1.x; Qs[(d0 + 5) * QSTR + i] = v1.y;
    Qs[(d0 + 6) * QSTR + i] = v1.z; Qs[(d0 + 7) * QSTR + i] = v1.w;
  }
  __syncthreads();

  const int ti = t >> 5;
  const int tj = t & 31;

  for (int c0 = 0; c0 < 2; c0++) {
    const int j0 = c0 * KC;
    {
      int j  = t >> 1;
      int d0 = (t & 1) * 32;
      int kj = j0 + j;
      const float* p = Kb + (size_t)kj * kQkvN + d0;
#pragma unroll
      for (int q = 0; q < 8; q++) {
        float4 v = {0.f, 0.f, 0.f, 0.f};
        if (kj < kTok) v = *(const float4*)(p + q * 4);
        int d = d0 + q * 4;
        KV[(d + 0) * KSTR + j] = v.x;
        KV[(d + 1) * KSTR + j] = v.y;
        KV[(d + 2) * KSTR + j] = v.z;
        KV[(d + 3) * KSTR + j] = v.w;
      }
    }
    __syncthreads();

    float acc[4][4] = {};
#pragma unroll 16
    for (int d = 0; d < 64; d++) {
      float4 av = *(const float4*)&Qs[d * QSTR + ti * 4];
      float4 bv = *(const float4*)&KV[d * KSTR + tj * 4];
      float a[4] = {av.x, av.y, av.z, av.w};
      float bb[4] = {bv.x, bv.y, bv.z, bv.w};
#pragma unroll
      for (int r = 0; r < 4; r++)
#pragma unroll
        for (int c = 0; c < 4; c++) acc[r][c] = fmaf(a[r], bb[c], acc[r][c]);
    }
#pragma unroll
    for (int r = 0; r < 4; r++)
#pragma unroll
      for (int c = 0; c < 4; c++)
        S[(ti * 4 + r) * SSTR + j0 + tj * 4 + c] = acc[r][c];
    __syncthreads();
  }

  {
    const int lane = tj;
#pragma unroll
    for (int r = 0; r < 4; r++) {
      int i  = ti * 4 + r;
      int qi = min(i0g + i, kTok - 1);
      const float* rp = g_rpb + ((size_t)h * kTok + qi) * kTok;
      float vals[7];
      float mx = -1e30f;
#pragma unroll
      for (int k = 0; k < 7; k++) {
        int j = lane + k * 32;
        float v = -1e30f;
        if (j < kTok) v = S[i * SSTR + j] + rp[j];
        vals[k] = v;
        mx = fmaxf(mx, v);
      }
#pragma unroll
      for (int o = 16; o; o >>= 1) mx = fmaxf(mx, __shfl_xor_sync(0xffffffffu, mx, o));
      float sum = 0.f;
#pragma unroll
      for (int k = 0; k < 7; k++) {
        int j = lane + k * 32;
        float e = (j < kTok) ? __expf(vals[k] - mx) : 0.f;
        vals[k] = e;
        sum += e;
      }
#pragma unroll
      for (int o = 16; o; o >>= 1) sum += __shfl_xor_sync(0xffffffffu, sum, o);
      float inv = 1.f / sum;
#pragma unroll
      for (int k = 0; k < 7; k++) {
        int j = lane + k * 32;
        S[i * SSTR + j] = (j < kTok) ? vals[k] * inv : 0.f;
      }
      S[i * SSTR + 224 + lane] = 0.f;
    }
  }
  __syncthreads();

  float accO[4][2] = {};
  for (int c0 = 0; c0 < 2; c0++) {
    const int j0 = c0 * KC;
    {
      int j  = t >> 1;
      int d0 = (t & 1) * 32;
      int vj = j0 + j;
      const float* p = Vb + (size_t)vj * kQkvN + d0;
#pragma unroll
      for (int q = 0; q < 8; q++) {
        float4 v = {0.f, 0.f, 0.f, 0.f};
        if (vj < kTok) v = *(const float4*)(p + q * 4);
        *(float4*)&KV[j * VSTR + d0 + q * 4] = v;
      }
    }
    __syncthreads();
#pragma unroll 16
    for (int jj = 0; jj < KC; jj++) {
      float p0 = S[(ti * 4 + 0) * SSTR + j0 + jj];
      float p1 = S[(ti * 4 + 1) * SSTR + j0 + jj];
      float p2 = S[(ti * 4 + 2) * SSTR + j0 + jj];
      float p3 = S[(ti * 4 + 3) * SSTR + j0 + jj];
      float2 bv = *(const float2*)&KV[jj * VSTR + tj * 2];
      accO[0][0] = fmaf(p0, bv.x, accO[0][0]); accO[0][1] = fmaf(p0, bv.y, accO[0][1]);
      accO[1][0] = fmaf(p1, bv.x, accO[1][0]); accO[1][1] = fmaf(p1, bv.y, accO[1][1]);
      accO[2][0] = fmaf(p2, bv.x, accO[2][0]); accO[2][1] = fmaf(p2, bv.y, accO[2][1]);
      accO[3][0] = fmaf(p3, bv.x, accO[3][0]); accO[3][1] = fmaf(p3, bv.y, accO[3][1]);
    }
    __syncthreads();
  }

#pragma unroll
  for (int r = 0; r < 4; r++) {
    int qi = i0g + ti * 4 + r;
    if (qi < kTok) {
      float* o = g_attn + ((size_t)b * kTok + qi) * kDim + h * 64 + tj * 2;
      o[0] = tf32_rna(accO[r][0]);
      o[1] = tf32_rna(accO[r][1]);
    }
  }
}

// ---------------------------------------------------------------------------
// Launch
// ---------------------------------------------------------------------------
extern "C" void kernel_launch(void* const* d_in, const int* in_sizes, int n_in,
                              void* d_out, int out_size) {
  const float* x         = (const float*)d_in[0];
  const float* qkv_w     = (const float*)d_in[1];
  const float* q_bias    = (const float*)d_in[2];
  const float* v_bias    = (const float*)d_in[3];
  const float* rpb_table = (const float*)d_in[4];
  const float* proj_w    = (const float*)d_in[5];
  const float* proj_b    = (const float*)d_in[6];
  const int*   rel_idx   = (const int*)d_in[7];
  float* out = (float*)d_out;

  float *qkv_ptr, *attn_ptr, *x_ptr, *wqkv_ptr, *wproj_ptr;
  cudaGetSymbolAddress((void**)&qkv_ptr, g_qkv);
  cudaGetSymbolAddress((void**)&attn_ptr, g_attn);
  cudaGetSymbolAddress((void**)&x_ptr, g_x);
  cudaGetSymbolAddress((void**)&wqkv_ptr, g_wqkv);
  cudaGetSymbolAddress((void**)&wproj_ptr, g_wproj);

  // (0) tf32-round GEMM inputs
  {
    int n4 = kM * kDim / 4;
    tf32_round_kernel<<<(n4 + 255) / 256, 256>>>(x, x_ptr, n4);
    n4 = kQkvN * kDim / 4;
    tf32_round_kernel<<<(n4 + 255) / 256, 256>>>(qkv_w, wqkv_ptr, n4);
    n4 = kDim * kDim / 4;
    tf32_round_kernel<<<(n4 + 255) / 256, 256>>>(proj_w, wproj_ptr, n4);
  }

  // (1) relative position bias expansion
  rpb_expand<<<(kTok * kTok + 255) / 256, 256>>>(rel_idx, rpb_table);

  // (2) QKV projection
  cudaFuncSetAttribute(gemm_tf32_pipe<0>, cudaFuncAttributeMaxDynamicSharedMemorySize,
                       kGemmSmemBytes);
  {
    dim3 grid(kQkvN / 128, (kM + 127) / 128);
    gemm_tf32_pipe<0><<<grid, 256, kGemmSmemBytes>>>(x_ptr, wqkv_ptr, qkv_ptr,
                                                     kM, kDim, kQkvN, q_bias, v_bias);
  }

  // (3) attention
  cudaFuncSetAttribute(attn_kernel, cudaFuncAttributeMaxDynamicSharedMemorySize,
                       kAttnSmemBytes);
  attn_kernel<<<dim3(7, kBatch * kHeads), 256, kAttnSmemBytes>>>();

  // (4) output projection
  cudaFuncSetAttribute(gemm_tf32_pipe<1>, cudaFuncAttributeMaxDynamicSharedMemorySize,
                       kGemmSmemBytes);
  {
    dim3 grid(kDim / 128, (kM + 127) / 128);
    gemm_tf32_pipe<1><<<grid, 256, kGemmSmemBytes>>>(attn_ptr, wproj_ptr, out,
                                                     kM, kDim, kDim, proj_b, nullptr);
  }
}

// round 4
// speedup vs baseline: 2.6730x; 1.2260x over previous
#include <cuda_runtime.h>
#include <cstdint>

// ---------------------------------------------------------------------------
// Problem constants
// ---------------------------------------------------------------------------
namespace {
constexpr int kHeads = 12;
constexpr int kTok   = 197;               // N_PATCH + 1
constexpr int kDim   = 768;
constexpr int kBatch = 64;
constexpr int kM     = kBatch * kTok;     // 12608
constexpr int kQkvN  = 3 * kDim;          // 2304
constexpr float kScale = 0.125f;          // hd^-0.5
}  // namespace

// Scratch (static device globals; no runtime allocation allowed)
__device__ float g_qkv[(size_t)kM * kQkvN];             // (B, N, 3C), tf32-rounded
__device__ float g_attn[(size_t)kM * kDim];             // (B, N, C), tf32-rounded
__device__ float g_rpb[(size_t)kHeads * kTok * kTok];   // (H, N, N)
__device__ float g_x[(size_t)kM * kDim];                // tf32-rounded x
__device__ float g_wqkv[(size_t)kQkvN * kDim];          // tf32-rounded qkv_w
__device__ float g_wproj[(size_t)kDim * kDim];          // tf32-rounded proj_w

__device__ __forceinline__ float tf32_rna(float x) {
  uint32_t r;
  asm("cvt.rna.tf32.f32 %0, %1;" : "=r"(r) : "f"(x));
  return __uint_as_float(r);
}

// ---------------------------------------------------------------------------
// Elementwise tf32 rounding (n divisible by 4)
// ---------------------------------------------------------------------------
__global__ void tf32_round_kernel(const float* __restrict__ in, float* __restrict__ out,
                                  int n4) {
  int i = blockIdx.x * blockDim.x + threadIdx.x;
  if (i >= n4) return;
  float4 v = ((const float4*)in)[i];
  v.x = tf32_rna(v.x); v.y = tf32_rna(v.y);
  v.z = tf32_rna(v.z); v.w = tf32_rna(v.w);
  ((float4*)out)[i] = v;
}

// ---------------------------------------------------------------------------
// Relative position bias expansion: g_rpb[h][i][j] = table[idx[i][j]][h]
// ---------------------------------------------------------------------------
__global__ void rpb_expand(const int* __restrict__ idx, const float* __restrict__ tbl) {
  int t = blockIdx.x * blockDim.x + threadIdx.x;
  if (t >= kTok * kTok) return;
  int id = idx[t];
#pragma unroll
  for (int h = 0; h < kHeads; h++)
    g_rpb[(size_t)h * kTok * kTok + t] = tbl[id * kHeads + h];
}

// ---------------------------------------------------------------------------
// mma.sync m16n8k8 tf32 helper (fragment conventions per PTX ISA)
// ---------------------------------------------------------------------------
__device__ __forceinline__ void mma_tf32(float (&d)[4], const float* a, const float* b) {
  uint32_t a0 = __float_as_uint(a[0]), a1 = __float_as_uint(a[1]);
  uint32_t a2 = __float_as_uint(a[2]), a3 = __float_as_uint(a[3]);
  uint32_t b0 = __float_as_uint(b[0]), b1 = __float_as_uint(b[1]);
  asm volatile(
      "mma.sync.aligned.m16n8k8.row.col.f32.tf32.tf32.f32 "
      "{%0,%1,%2,%3}, {%4,%5,%6,%7}, {%8,%9}, {%0,%1,%2,%3};"
      : "+f"(d[0]), "+f"(d[1]), "+f"(d[2]), "+f"(d[3])
      : "r"(a0), "r"(a1), "r"(a2), "r"(a3), "r"(b0), "r"(b1));
}

// ---------------------------------------------------------------------------
// TF32 tensor-core GEMM, cp.async 4-stage pipeline (as R3).
// MODE 0 epilogue additionally rounds outputs to tf32 (consumed by attn mma).
// ---------------------------------------------------------------------------
namespace {
constexpr int kStages      = 4;
constexpr int kSmStride    = 20;
constexpr int kStageFloats = 2 * 128 * kSmStride;
constexpr int kGemmSmemBytes = kStages * kStageFloats * 4;  // 81920
}  // namespace

__device__ __forceinline__ void cp_async16(uint32_t dst, const void* src, bool pred) {
  int sz = pred ? 16 : 0;
  asm volatile("cp.async.ca.shared.global [%0], [%1], 16, %2;"
               :: "r"(dst), "l"(src), "r"(sz));
}
__device__ __forceinline__ void cp_commit() { asm volatile("cp.async.commit_group;"); }
__device__ __forceinline__ void cp_wait2()  { asm volatile("cp.async.wait_group 2;"); }

template <int MODE>
__global__ __launch_bounds__(256)
void gemm_tf32_pipe(const float* __restrict__ A, const float* __restrict__ W,
                    float* __restrict__ C, int M, int K, int N,
                    const float* __restrict__ b0, const float* __restrict__ b1) {
  extern __shared__ float sm[];

  const int t    = threadIdx.x;
  const int lane = t & 31;
  const int wid  = t >> 5;
  const int wm   = (wid >> 2) * 64;
  const int wn   = (wid & 3) * 32;
  const int m0   = blockIdx.y * 128;
  const int n0   = blockIdx.x * 128;

  const uint32_t smem_base = (uint32_t)__cvta_generic_to_shared(sm);

  auto issue_stage = [&](int kb_idx) {
    int kb = kb_idx * 16;
    uint32_t uA = smem_base + (uint32_t)((kb_idx & 3) * kStageFloats) * 4;
    uint32_t uB = uA + 128 * kSmStride * 4;
#pragma unroll
    for (int i = 0; i < 2; i++) {
      int idx = t + i * 256;
      int row = idx >> 2;
      int c4  = (idx & 3) * 4;
      uint32_t soff = (uint32_t)(row * kSmStride + c4) * 4;
      int mg = m0 + row;
      cp_async16(uA + soff, A + (size_t)mg * K + kb + c4, mg < M);
      int ng = n0 + row;
      cp_async16(uB + soff, W + (size_t)ng * K + kb + c4, true);
    }
  };

  const int nkb = K / 16;
#pragma unroll
  for (int s = 0; s < kStages - 1; s++) {
    issue_stage(s);
    cp_commit();
  }

  float acc[4][4][4] = {};
  const int lm = lane >> 2;
  const int lk = lane & 3;

  for (int kb = 0; kb < nkb; kb++) {
    cp_wait2();
    __syncthreads();

    if (kb + kStages - 1 < nkb) issue_stage(kb + kStages - 1);
    cp_commit();

    const float* As = sm + (kb & 3) * kStageFloats;
    const float* Bs = As + 128 * kSmStride;

#pragma unroll
    for (int ks = 0; ks < 2; ks++) {
      float af[4][4];
      float bf[4][2];
#pragma unroll
      for (int mt = 0; mt < 4; mt++) {
        int r = wm + mt * 16 + lm;
        int c = ks * 8 + lk;
        af[mt][0] = As[r * kSmStride + c];
        af[mt][1] = As[(r + 8) * kSmStride + c];
        af[mt][2] = As[r * kSmStride + c + 4];
        af[mt][3] = As[(r + 8) * kSmStride + c + 4];
      }
#pragma unroll
      for (int nt = 0; nt < 4; nt++) {
        int r = wn + nt * 8 + lm;
        int c = ks * 8 + lk;
        bf[nt][0] = Bs[r * kSmStride + c];
        bf[nt][1] = Bs[r * kSmStride + c + 4];
      }
#pragma unroll
      for (int mt = 0; mt < 4; mt++)
#pragma unroll
        for (int nt = 0; nt < 4; nt++)
          mma_tf32(acc[mt][nt], af[mt], bf[nt]);
    }
  }

  const int mrow = lane >> 2;
  const int ncol = (lane & 3) * 2;
#pragma unroll
  for (int mt = 0; mt < 4; mt++) {
#pragma unroll
    for (int half = 0; half < 2; half++) {
      int m = m0 + wm + mt * 16 + mrow + half * 8;
      if (m >= M) continue;
#pragma unroll
      for (int nt = 0; nt < 4; nt++) {
        int n = n0 + wn + nt * 8 + ncol;
        float v0 = acc[mt][nt][half * 2 + 0];
        float v1 = acc[mt][nt][half * 2 + 1];
        if (MODE == 0) {
          float bias0 = (n < kDim) ? b0[n] : ((n < 2 * kDim) ? 0.f : b1[n - 2 * kDim]);
          float bias1 = (n + 1 < kDim) ? b0[n + 1]
                        : ((n + 1 < 2 * kDim) ? 0.f : b1[n + 1 - 2 * kDim]);
          v0 += bias0;
          v1 += bias1;
          if (n < kDim) { v0 *= kScale; v1 *= kScale; }
          v0 = tf32_rna(v0);   // consumed by tensor-core attention
          v1 = tf32_rna(v1);
        } else {
          v0 += b0[n];
          v1 += b0[n + 1];
        }
        *(float2*)(C + (size_t)m * N + n) = make_float2(v0, v1);
      }
    }
  }
}

// ---------------------------------------------------------------------------
// Tensor-core attention. One block = (b, h) x 32 query rows, 8 warps.
// Phase A: S[32x256] = Q @ K^T via mma (warp tile 16x32, Q frags hoisted)
// Phase B: softmax(S + rpb) in fp32, probabilities written back tf32-rounded
// Phase C: O[32x64] = P @ V via mma (warp tile 16x16, V staged transposed)
// SMEM strides 68/132/260 are all == 4 (mod 32): fragment gathers map to
// addr%32 = 4*row+col which covers 0..31 -> bank-conflict-free.
// ---------------------------------------------------------------------------
namespace {
constexpr int TQ   = 32;
constexpr int KC   = 128;
constexpr int SSTR = 260;   // S row stride
constexpr int QSTR = 68;    // Qs row stride (row-major 32x64)
constexpr int KSTR = 68;    // Ks row stride (row-major 128x64)
constexpr int VSTR = 132;   // Vs row stride (transposed 64x128)
constexpr int kKVFloats = (128 * KSTR > 64 * VSTR) ? 128 * KSTR : 64 * VSTR;  // 8704
constexpr int kAttnSmemFloats = TQ * SSTR + TQ * QSTR + kKVFloats;  // 8320+2176+8704
constexpr int kAttnSmemBytes  = kAttnSmemFloats * 4;                // 76800
}  // namespace

__global__ __launch_bounds__(256)
void attn_kernel() {
  extern __shared__ float smA[];
  float* S  = smA;                 // [32][SSTR]
  float* Qs = smA + TQ * SSTR;     // [32][QSTR]
  float* KV = Qs + TQ * QSTR;      // Ks [128][KSTR]  /  Vs [64][VSTR]

  const int t    = threadIdx.x;
  const int lane = t & 31;
  const int w    = t >> 5;
  const int tile = blockIdx.x;
  const int bh   = blockIdx.y;
  const int b    = bh / kHeads;
  const int h    = bh - b * kHeads;
  const int i0g  = tile * TQ;

  const float* Qb = g_qkv + (size_t)b * kTok * kQkvN + h * 64;
  const float* Kb = Qb + kDim;
  const float* Vb = Qb + 2 * kDim;

  const int lm = lane >> 2;   // 0..7
  const int lk = lane & 3;    // 0..3
  const int mrow = (w & 1) * 16;       // warp m offset within 32 rows

  // ---- load Q tile row-major: Qs[i][d] ----
  {
    int i  = t >> 3;
    int d0 = (t & 7) * 8;
    int qi = i0g + i;
    float4 v0 = {0.f, 0.f, 0.f, 0.f}, v1 = {0.f, 0.f, 0.f, 0.f};
    if (qi < kTok) {
      const float* p = Qb + (size_t)qi * kQkvN + d0;
      v0 = *(const float4*)p;
      v1 = *(const float4*)(p + 4);
    }
    *(float4*)&Qs[i * QSTR + d0]     = v0;
    *(float4*)&Qs[i * QSTR + d0 + 4] = v1;
  }
  __syncthreads();

  // ---- hoist Q fragments: aq[ks][4], ks = k-step over d (64 = 8 steps) ----
  float aq[8][4];
#pragma unroll
  for (int ks = 0; ks < 8; ks++) {
    int r = mrow + lm;
    int c = ks * 8 + lk;
    aq[ks][0] = Qs[r * QSTR + c];
    aq[ks][1] = Qs[(r + 8) * QSTR + c];
    aq[ks][2] = Qs[r * QSTR + c + 4];
    aq[ks][3] = Qs[(r + 8) * QSTR + c + 4];
  }

  // ---- Phase A: S = Q @ K^T ----
  for (int c0 = 0; c0 < 2; c0++) {
    const int j0 = c0 * KC;
    {  // load K chunk row-major: Ks[j][d], zero-fill past kTok
      int j  = t >> 1;
      int d0 = (t & 1) * 32;
      int kj = j0 + j;
      const float* p = Kb + (size_t)kj * kQkvN + d0;
#pragma unroll
      for (int q = 0; q < 8; q++) {
        float4 v = {0.f, 0.f, 0.f, 0.f};
        if (kj < kTok) v = *(const float4*)(p + q * 4);
        *(float4*)&KV[j * KSTR + d0 + q * 4] = v;
      }
    }
    __syncthreads();

    float acc[4][4] = {};
#pragma unroll
    for (int ks = 0; ks < 8; ks++) {
#pragma unroll
      for (int nt = 0; nt < 4; nt++) {
        int n = ((w >> 1) * 4 + nt) * 8 + lm;   // key index within chunk
        int c = ks * 8 + lk;
        float bf[2] = {KV[n * KSTR + c], KV[n * KSTR + c + 4]};
        mma_tf32(acc[nt], aq[ks], bf);
      }
    }
#pragma unroll
    for (int nt = 0; nt < 4; nt++) {
      int col = j0 + ((w >> 1) * 4 + nt) * 8 + lk * 2;
      int r   = mrow + lm;
      *(float2*)&S[r * SSTR + col]       = make_float2(acc[nt][0], acc[nt][1]);
      *(float2*)&S[(r + 8) * SSTR + col] = make_float2(acc[nt][2], acc[nt][3]);
    }
    __syncthreads();
  }

  // ---- Phase B: softmax(S + rpb); write probs tf32-rounded ----
  {
#pragma unroll
    for (int r = 0; r < 4; r++) {
      int i  = w * 4 + r;
      int qi = min(i0g + i, kTok - 1);
      const float* rp = g_rpb + ((size_t)h * kTok + qi) * kTok;
      float vals[7];
      float mx = -1e30f;
#pragma unroll
      for (int k = 0; k < 7; k++) {
        int j = lane + k * 32;
        float v = -1e30f;
        if (j < kTok) v = S[i * SSTR + j] + rp[j];
        vals[k] = v;
        mx = fmaxf(mx, v);
      }
#pragma unroll
      for (int o = 16; o; o >>= 1) mx = fmaxf(mx, __shfl_xor_sync(0xffffffffu, mx, o));
      float sum = 0.f;
#pragma unroll
      for (int k = 0; k < 7; k++) {
        int j = lane + k * 32;
        float e = (j < kTok) ? __expf(vals[k] - mx) : 0.f;
        vals[k] = e;
        sum += e;
      }
#pragma unroll
      for (int o = 16; o; o >>= 1) sum += __shfl_xor_sync(0xffffffffu, sum, o);
      float inv = 1.f / sum;
#pragma unroll
      for (int k = 0; k < 7; k++) {
        int j = lane + k * 32;
        S[i * SSTR + j] = (j < kTok) ? tf32_rna(vals[k] * inv) : 0.f;
      }
      S[i * SSTR + 224 + lane] = 0.f;   // zero pad cols 224..255
    }
  }
  __syncthreads();

  // ---- Phase C: O = P @ V ----
  float accO[2][4] = {};
  for (int c0 = 0; c0 < 2; c0++) {
    const int j0 = c0 * KC;
    {  // load V chunk transposed: Vs[d][j], zero-fill past kTok
      int j  = t >> 1;
      int d0 = (t & 1) * 32;
      int vj = j0 + j;
      const float* p = Vb + (size_t)vj * kQkvN + d0;
#pragma unroll
      for (int q = 0; q < 8; q++) {
        float4 v = {0.f, 0.f, 0.f, 0.f};
        if (vj < kTok) v = *(const float4*)(p + q * 4);
        int d = d0 + q * 4;
        KV[(d + 0) * VSTR + j] = v.x;
        KV[(d + 1) * VSTR + j] = v.y;
        KV[(d + 2) * VSTR + j] = v.z;
        KV[(d + 3) * VSTR + j] = v.w;
      }
    }
    __syncthreads();

#pragma unroll
    for (int ks = 0; ks < 16; ks++) {
      int r = mrow + lm;
      int c = j0 + ks * 8 + lk;
      float ap[4];
      ap[0] = S[r * SSTR + c];
      ap[1] = S[(r + 8) * SSTR + c];
      ap[2] = S[r * SSTR + c + 4];
      ap[3] = S[(r + 8) * SSTR + c + 4];
#pragma unroll
      for (int nt = 0; nt < 2; nt++) {
        int n = ((w >> 1) * 2 + nt) * 8 + lm;   // d index 0..63
        int k = ks * 8 + lk;                    // j within chunk
        float bf[2] = {KV[n * VSTR + k], KV[n * VSTR + k + 4]};
        mma_tf32(accO[nt], ap, bf);
      }
    }
    __syncthreads();
  }

  // ---- epilogue: write g_attn (tf32-rounded for proj GEMM) ----
#pragma unroll
  for (int nt = 0; nt < 2; nt++) {
    int dcol = ((w >> 1) * 2 + nt) * 8 + lk * 2;
#pragma unroll
    for (int half = 0; half < 2; half++) {
      int i = i0g + mrow + lm + half * 8;
      if (i < kTok) {
        float v0 = tf32_rna(accO[nt][half * 2 + 0]);
        float v1 = tf32_rna(accO[nt][half * 2 + 1]);
        *(float2*)(g_attn + ((size_t)b * kTok + i) * kDim + h * 64 + dcol) =
            make_float2(v0, v1);
      }
    }
  }
}

// ---------------------------------------------------------------------------
// Launch
// ---------------------------------------------------------------------------
extern "C" void kernel_launch(void* const* d_in, const int* in_sizes, int n_in,
                              void* d_out, int out_size) {
  const float* x         = (const float*)d_in[0];
  const float* qkv_w     = (const float*)d_in[1];
  const float* q_bias    = (const float*)d_in[2];
  const float* v_bias    = (const float*)d_in[3];
  const float* rpb_table = (const float*)d_in[4];
  const float* proj_w    = (const float*)d_in[5];
  const float* proj_b    = (const float*)d_in[6];
  const int*   rel_idx   = (const int*)d_in[7];
  float* out = (float*)d_out;

  float *qkv_ptr, *attn_ptr, *x_ptr, *wqkv_ptr, *wproj_ptr;
  cudaGetSymbolAddress((void**)&qkv_ptr, g_qkv);
  cudaGetSymbolAddress((void**)&attn_ptr, g_attn);
  cudaGetSymbolAddress((void**)&x_ptr, g_x);
  cudaGetSymbolAddress((void**)&wqkv_ptr, g_wqkv);
  cudaGetSymbolAddress((void**)&wproj_ptr, g_wproj);

  // (0) tf32-round GEMM inputs
  {
    int n4 = kM * kDim / 4;
    tf32_round_kernel<<<(n4 + 255) / 256, 256>>>(x, x_ptr, n4);
    n4 = kQkvN * kDim / 4;
    tf32_round_kernel<<<(n4 + 255) / 256, 256>>>(qkv_w, wqkv_ptr, n4);
    n4 = kDim * kDim / 4;
    tf32_round_kernel<<<(n4 + 255) / 256, 256>>>(proj_w, wproj_ptr, n4);
  }

  // (1) relative position bias expansion
  rpb_expand<<<(kTok * kTok + 255) / 256, 256>>>(rel_idx, rpb_table);

  // (2) QKV projection (epilogue rounds to tf32)
  cudaFuncSetAttribute(gemm_tf32_pipe<0>, cudaFuncAttributeMaxDynamicSharedMemorySize,
                       kGemmSmemBytes);
  {
    dim3 grid(kQkvN / 128, (kM + 127) / 128);
    gemm_tf32_pipe<0><<<grid, 256, kGemmSmemBytes>>>(x_ptr, wqkv_ptr, qkv_ptr,
                                                     kM, kDim, kQkvN, q_bias, v_bias);
  }

  // (3) tensor-core attention
  cudaFuncSetAttribute(attn_kernel, cudaFuncAttributeMaxDynamicSharedMemorySize,
                       kAttnSmemBytes);
  attn_kernel<<<dim3(7, kBatch * kHeads), 256, kAttnSmemBytes>>>();

  // (4) output projection
  cudaFuncSetAttribute(gemm_tf32_pipe<1>, cudaFuncAttributeMaxDynamicSharedMemorySize,
                       kGemmSmemBytes);
  {
    dim3 grid(kDim / 128, (kM + 127) / 128);
    gemm_tf32_pipe<1><<<grid, 256, kGemmSmemBytes>>>(attn_ptr, wproj_ptr, out,
                                                     kM, kDim, kDim, proj_b, nullptr);
  }
}

// round 5
// speedup vs baseline: 2.7194x; 1.0174x over previous
#include <cuda_runtime.h>
#include <cstdint>

// ---------------------------------------------------------------------------
// Problem constants
// ---------------------------------------------------------------------------
namespace {
constexpr int kHeads = 12;
constexpr int kTok   = 197;               // N_PATCH + 1
constexpr int kDim   = 768;
constexpr int kBatch = 64;
constexpr int kM     = kBatch * kTok;     // 12608
constexpr int kQkvN  = 3 * kDim;          // 2304
constexpr float kScale = 0.125f;          // hd^-0.5
}  // namespace

// Scratch (static device globals; no runtime allocation allowed)
__device__ float g_qkv[(size_t)kM * kQkvN];             // (B, N, 3C), tf32-rounded
__device__ float g_attn[(size_t)kM * kDim];             // (B, N, C), tf32-rounded
__device__ float g_rpb[(size_t)kHeads * kTok * kTok];   // (H, N, N)
__device__ float g_x[(size_t)kM * kDim];                // tf32-rounded x
__device__ float g_wqkv[(size_t)kQkvN * kDim];          // tf32-rounded qkv_w
__device__ float g_wproj[(size_t)kDim * kDim];          // tf32-rounded proj_w

__device__ __forceinline__ float tf32_rna(float x) {
  uint32_t r;
  asm("cvt.rna.tf32.f32 %0, %1;" : "=r"(r) : "f"(x));
  return __uint_as_float(r);
}

// ---------------------------------------------------------------------------
// Elementwise tf32 rounding (n divisible by 4)
// ---------------------------------------------------------------------------
__global__ void tf32_round_kernel(const float* __restrict__ in, float* __restrict__ out,
                                  int n4) {
  int i = blockIdx.x * blockDim.x + threadIdx.x;
  if (i >= n4) return;
  float4 v = ((const float4*)in)[i];
  v.x = tf32_rna(v.x); v.y = tf32_rna(v.y);
  v.z = tf32_rna(v.z); v.w = tf32_rna(v.w);
  ((float4*)out)[i] = v;
}

// ---------------------------------------------------------------------------
// Relative position bias expansion: g_rpb[h][i][j] = table[idx[i][j]][h]
// ---------------------------------------------------------------------------
__global__ void rpb_expand(const int* __restrict__ idx, const float* __restrict__ tbl) {
  int t = blockIdx.x * blockDim.x + threadIdx.x;
  if (t >= kTok * kTok) return;
  int id = idx[t];
#pragma unroll
  for (int h = 0; h < kHeads; h++)
    g_rpb[(size_t)h * kTok * kTok + t] = tbl[id * kHeads + h];
}

// ---------------------------------------------------------------------------
// mma.sync m16n8k8 tf32 helper (fragment conventions per PTX ISA)
// ---------------------------------------------------------------------------
__device__ __forceinline__ void mma_tf32(float (&d)[4], const float* a, const float* b) {
  uint32_t a0 = __float_as_uint(a[0]), a1 = __float_as_uint(a[1]);
  uint32_t a2 = __float_as_uint(a[2]), a3 = __float_as_uint(a[3]);
  uint32_t b0 = __float_as_uint(b[0]), b1 = __float_as_uint(b[1]);
  asm volatile(
      "mma.sync.aligned.m16n8k8.row.col.f32.tf32.tf32.f32 "
      "{%0,%1,%2,%3}, {%4,%5,%6,%7}, {%8,%9}, {%0,%1,%2,%3};"
      : "+f"(d[0]), "+f"(d[1]), "+f"(d[2]), "+f"(d[3])
      : "r"(a0), "r"(a1), "r"(a2), "r"(a3), "r"(b0), "r"(b1));
}

// ---------------------------------------------------------------------------
// TF32 tensor-core GEMM, cp.async 4-stage pipeline.
// __launch_bounds__(256, 2): cap regs at 128 so 2 CTAs co-reside per SM
// (smem 80KB x 2 = 160KB <= 228KB) -> 4 warps per scheduler for latency hiding.
// MODE 0 epilogue additionally rounds outputs to tf32 (consumed by attn mma).
// ---------------------------------------------------------------------------
namespace {
constexpr int kStages      = 4;
constexpr int kSmStride    = 20;
constexpr int kStageFloats = 2 * 128 * kSmStride;
constexpr int kGemmSmemBytes = kStages * kStageFloats * 4;  // 81920
}  // namespace

__device__ __forceinline__ void cp_async16(uint32_t dst, const void* src, bool pred) {
  int sz = pred ? 16 : 0;
  asm volatile("cp.async.ca.shared.global [%0], [%1], 16, %2;"
               :: "r"(dst), "l"(src), "r"(sz));
}
__device__ __forceinline__ void cp_commit() { asm volatile("cp.async.commit_group;"); }
__device__ __forceinline__ void cp_wait2()  { asm volatile("cp.async.wait_group 2;"); }

template <int MODE>
__global__ __launch_bounds__(256, 2)
void gemm_tf32_pipe(const float* __restrict__ A, const float* __restrict__ W,
                    float* __restrict__ C, int M, int K, int N,
                    const float* __restrict__ b0, const float* __restrict__ b1) {
  extern __shared__ float sm[];

  const int t    = threadIdx.x;
  const int lane = t & 31;
  const int wid  = t >> 5;
  const int wm   = (wid >> 2) * 64;
  const int wn   = (wid & 3) * 32;
  const int m0   = blockIdx.y * 128;
  const int n0   = blockIdx.x * 128;

  const uint32_t smem_base = (uint32_t)__cvta_generic_to_shared(sm);

  auto issue_stage = [&](int kb_idx) {
    int kb = kb_idx * 16;
    uint32_t uA = smem_base + (uint32_t)((kb_idx & 3) * kStageFloats) * 4;
    uint32_t uB = uA + 128 * kSmStride * 4;
#pragma unroll
    for (int i = 0; i < 2; i++) {
      int idx = t + i * 256;
      int row = idx >> 2;
      int c4  = (idx & 3) * 4;
      uint32_t soff = (uint32_t)(row * kSmStride + c4) * 4;
      int mg = m0 + row;
      cp_async16(uA + soff, A + (size_t)mg * K + kb + c4, mg < M);
      int ng = n0 + row;
      cp_async16(uB + soff, W + (size_t)ng * K + kb + c4, true);
    }
  };

  const int nkb = K / 16;
#pragma unroll
  for (int s = 0; s < kStages - 1; s++) {
    issue_stage(s);
    cp_commit();
  }

  float acc[4][4][4] = {};
  const int lm = lane >> 2;
  const int lk = lane & 3;

  for (int kb = 0; kb < nkb; kb++) {
    cp_wait2();
    __syncthreads();

    if (kb + kStages - 1 < nkb) issue_stage(kb + kStages - 1);
    cp_commit();

    const float* As = sm + (kb & 3) * kStageFloats;
    const float* Bs = As + 128 * kSmStride;

#pragma unroll
    for (int ks = 0; ks < 2; ks++) {
      float af[4][4];
      float bf[4][2];
#pragma unroll
      for (int mt = 0; mt < 4; mt++) {
        int r = wm + mt * 16 + lm;
        int c = ks * 8 + lk;
        af[mt][0] = As[r * kSmStride + c];
        af[mt][1] = As[(r + 8) * kSmStride + c];
        af[mt][2] = As[r * kSmStride + c + 4];
        af[mt][3] = As[(r + 8) * kSmStride + c + 4];
      }
#pragma unroll
      for (int nt = 0; nt < 4; nt++) {
        int r = wn + nt * 8 + lm;
        int c = ks * 8 + lk;
        bf[nt][0] = Bs[r * kSmStride + c];
        bf[nt][1] = Bs[r * kSmStride + c + 4];
      }
#pragma unroll
      for (int mt = 0; mt < 4; mt++)
#pragma unroll
        for (int nt = 0; nt < 4; nt++)
          mma_tf32(acc[mt][nt], af[mt], bf[nt]);
    }
  }

  const int mrow = lane >> 2;
  const int ncol = (lane & 3) * 2;
#pragma unroll
  for (int mt = 0; mt < 4; mt++) {
#pragma unroll
    for (int half = 0; half < 2; half++) {
      int m = m0 + wm + mt * 16 + mrow + half * 8;
      if (m >= M) continue;
#pragma unroll
      for (int nt = 0; nt < 4; nt++) {
        int n = n0 + wn + nt * 8 + ncol;
        float v0 = acc[mt][nt][half * 2 + 0];
        float v1 = acc[mt][nt][half * 2 + 1];
        if (MODE == 0) {
          float bias0 = (n < kDim) ? b0[n] : ((n < 2 * kDim) ? 0.f : b1[n - 2 * kDim]);
          float bias1 = (n + 1 < kDim) ? b0[n + 1]
                        : ((n + 1 < 2 * kDim) ? 0.f : b1[n + 1 - 2 * kDim]);
          v0 += bias0;
          v1 += bias1;
          if (n < kDim) { v0 *= kScale; v1 *= kScale; }
          v0 = tf32_rna(v0);   // consumed by tensor-core attention
          v1 = tf32_rna(v1);
        } else {
          v0 += b0[n];
          v1 += b0[n + 1];
        }
        *(float2*)(C + (size_t)m * N + n) = make_float2(v0, v1);
      }
    }
  }
}

// ---------------------------------------------------------------------------
// Tensor-core attention (as R4) + __launch_bounds__(256, 2) for 2 CTAs/SM
// (smem 76.8KB x 2 = 153.6KB fits).
// ---------------------------------------------------------------------------
namespace {
constexpr int TQ   = 32;
constexpr int KC   = 128;
constexpr int SSTR = 260;   // S row stride
constexpr int QSTR = 68;    // Qs row stride (row-major 32x64)
constexpr int KSTR = 68;    // Ks row stride (row-major 128x64)
constexpr int VSTR = 132;   // Vs row stride (transposed 64x128)
constexpr int kKVFloats = (128 * KSTR > 64 * VSTR) ? 128 * KSTR : 64 * VSTR;  // 8704
constexpr int kAttnSmemFloats = TQ * SSTR + TQ * QSTR + kKVFloats;
constexpr int kAttnSmemBytes  = kAttnSmemFloats * 4;                // 76800
}  // namespace

__global__ __launch_bounds__(256, 2)
void attn_kernel() {
  extern __shared__ float smA[];
  float* S  = smA;                 // [32][SSTR]
  float* Qs = smA + TQ * SSTR;     // [32][QSTR]
  float* KV = Qs + TQ * QSTR;      // Ks [128][KSTR]  /  Vs [64][VSTR]

  const int t    = threadIdx.x;
  const int lane = t & 31;
  const int w    = t >> 5;
  const int tile = blockIdx.x;
  const int bh   = blockIdx.y;
  const int b    = bh / kHeads;
  const int h    = bh - b * kHeads;
  const int i0g  = tile * TQ;

  const float* Qb = g_qkv + (size_t)b * kTok * kQkvN + h * 64;
  const float* Kb = Qb + kDim;
  const float* Vb = Qb + 2 * kDim;

  const int lm = lane >> 2;   // 0..7
  const int lk = lane & 3;    // 0..3
  const int mrow = (w & 1) * 16;       // warp m offset within 32 rows

  // ---- load Q tile row-major: Qs[i][d] ----
  {
    int i  = t >> 3;
    int d0 = (t & 7) * 8;
    int qi = i0g + i;
    float4 v0 = {0.f, 0.f, 0.f, 0.f}, v1 = {0.f, 0.f, 0.f, 0.f};
    if (qi < kTok) {
      const float* p = Qb + (size_t)qi * kQkvN + d0;
      v0 = *(const float4*)p;
      v1 = *(const float4*)(p + 4);
    }
    *(float4*)&Qs[i * QSTR + d0]     = v0;
    *(float4*)&Qs[i * QSTR + d0 + 4] = v1;
  }
  __syncthreads();

  // ---- hoist Q fragments ----
  float aq[8][4];
#pragma unroll
  for (int ks = 0; ks < 8; ks++) {
    int r = mrow + lm;
    int c = ks * 8 + lk;
    aq[ks][0] = Qs[r * QSTR + c];
    aq[ks][1] = Qs[(r + 8) * QSTR + c];
    aq[ks][2] = Qs[r * QSTR + c + 4];
    aq[ks][3] = Qs[(r + 8) * QSTR + c + 4];
  }

  // ---- Phase A: S = Q @ K^T ----
  for (int c0 = 0; c0 < 2; c0++) {
    const int j0 = c0 * KC;
    {  // load K chunk row-major: Ks[j][d], zero-fill past kTok
      int j  = t >> 1;
      int d0 = (t & 1) * 32;
      int kj = j0 + j;
      const float* p = Kb + (size_t)kj * kQkvN + d0;
#pragma unroll
      for (int q = 0; q < 8; q++) {
        float4 v = {0.f, 0.f, 0.f, 0.f};
        if (kj < kTok) v = *(const float4*)(p + q * 4);
        *(float4*)&KV[j * KSTR + d0 + q * 4] = v;
      }
    }
    __syncthreads();

    float acc[4][4] = {};
#pragma unroll
    for (int ks = 0; ks < 8; ks++) {
#pragma unroll
      for (int nt = 0; nt < 4; nt++) {
        int n = ((w >> 1) * 4 + nt) * 8 + lm;   // key index within chunk
        int c = ks * 8 + lk;
        float bf[2] = {KV[n * KSTR + c], KV[n * KSTR + c + 4]};
        mma_tf32(acc[nt], aq[ks], bf);
      }
    }
#pragma unroll
    for (int nt = 0; nt < 4; nt++) {
      int col = j0 + ((w >> 1) * 4 + nt) * 8 + lk * 2;
      int r   = mrow + lm;
      *(float2*)&S[r * SSTR + col]       = make_float2(acc[nt][0], acc[nt][1]);
      *(float2*)&S[(r + 8) * SSTR + col] = make_float2(acc[nt][2], acc[nt][3]);
    }
    __syncthreads();
  }

  // ---- Phase B: softmax(S + rpb); write probs tf32-rounded ----
  {
#pragma unroll
    for (int r = 0; r < 4; r++) {
      int i  = w * 4 + r;
      int qi = min(i0g + i, kTok - 1);
      const float* rp = g_rpb + ((size_t)h * kTok + qi) * kTok;
      float vals[7];
      float mx = -1e30f;
#pragma unroll
      for (int k = 0; k < 7; k++) {
        int j = lane + k * 32;
        float v = -1e30f;
        if (j < kTok) v = S[i * SSTR + j] + rp[j];
        vals[k] = v;
        mx = fmaxf(mx, v);
      }
#pragma unroll
      for (int o = 16; o; o >>= 1) mx = fmaxf(mx, __shfl_xor_sync(0xffffffffu, mx, o));
      float sum = 0.f;
#pragma unroll
      for (int k = 0; k < 7; k++) {
        int j = lane + k * 32;
        float e = (j < kTok) ? __expf(vals[k] - mx) : 0.f;
        vals[k] = e;
        sum += e;
      }
#pragma unroll
      for (int o = 16; o; o >>= 1) sum += __shfl_xor_sync(0xffffffffu, sum, o);
      float inv = 1.f / sum;
#pragma unroll
      for (int k = 0; k < 7; k++) {
        int j = lane + k * 32;
        S[i * SSTR + j] = (j < kTok) ? tf32_rna(vals[k] * inv) : 0.f;
      }
      S[i * SSTR + 224 + lane] = 0.f;   // zero pad cols 224..255
    }
  }
  __syncthreads();

  // ---- Phase C: O = P @ V ----
  float accO[2][4] = {};
  for (int c0 = 0; c0 < 2; c0++) {
    const int j0 = c0 * KC;
    {  // load V chunk transposed: Vs[d][j], zero-fill past kTok
      int j  = t >> 1;
      int d0 = (t & 1) * 32;
      int vj = j0 + j;
      const float* p = Vb + (size_t)vj * kQkvN + d0;
#pragma unroll
      for (int q = 0; q < 8; q++) {
        float4 v = {0.f, 0.f, 0.f, 0.f};
        if (vj < kTok) v = *(const float4*)(p + q * 4);
        int d = d0 + q * 4;
        KV[(d + 0) * VSTR + j] = v.x;
        KV[(d + 1) * VSTR + j] = v.y;
        KV[(d + 2) * VSTR + j] = v.z;
        KV[(d + 3) * VSTR + j] = v.w;
      }
    }
    __syncthreads();

#pragma unroll
    for (int ks = 0; ks < 16; ks++) {
      int r = mrow + lm;
      int c = j0 + ks * 8 + lk;
      float ap[4];
      ap[0] = S[r * SSTR + c];
      ap[1] = S[(r + 8) * SSTR + c];
      ap[2] = S[r * SSTR + c + 4];
      ap[3] = S[(r + 8) * SSTR + c + 4];
#pragma unroll
      for (int nt = 0; nt < 2; nt++) {
        int n = ((w >> 1) * 2 + nt) * 8 + lm;   // d index 0..63
        int k = ks * 8 + lk;                    // j within chunk
        float bf[2] = {KV[n * VSTR + k], KV[n * VSTR + k + 4]};
        mma_tf32(accO[nt], ap, bf);
      }
    }
    __syncthreads();
  }

  // ---- epilogue: write g_attn (tf32-rounded for proj GEMM) ----
#pragma unroll
  for (int nt = 0; nt < 2; nt++) {
    int dcol = ((w >> 1) * 2 + nt) * 8 + lk * 2;
#pragma unroll
    for (int half = 0; half < 2; half++) {
      int i = i0g + mrow + lm + half * 8;
      if (i < kTok) {
        float v0 = tf32_rna(accO[nt][half * 2 + 0]);
        float v1 = tf32_rna(accO[nt][half * 2 + 1]);
        *(float2*)(g_attn + ((size_t)b * kTok + i) * kDim + h * 64 + dcol) =
            make_float2(v0, v1);
      }
    }
  }
}

// ---------------------------------------------------------------------------
// Launch
// ---------------------------------------------------------------------------
extern "C" void kernel_launch(void* const* d_in, const int* in_sizes, int n_in,
                              void* d_out, int out_size) {
  const float* x         = (const float*)d_in[0];
  const float* qkv_w     = (const float*)d_in[1];
  const float* q_bias    = (const float*)d_in[2];
  const float* v_bias    = (const float*)d_in[3];
  const float* rpb_table = (const float*)d_in[4];
  const float* proj_w    = (const float*)d_in[5];
  const float* proj_b    = (const float*)d_in[6];
  const int*   rel_idx   = (const int*)d_in[7];
  float* out = (float*)d_out;

  float *qkv_ptr, *attn_ptr, *x_ptr, *wqkv_ptr, *wproj_ptr;
  cudaGetSymbolAddress((void**)&qkv_ptr, g_qkv);
  cudaGetSymbolAddress((void**)&attn_ptr, g_attn);
  cudaGetSymbolAddress((void**)&x_ptr, g_x);
  cudaGetSymbolAddress((void**)&wqkv_ptr, g_wqkv);
  cudaGetSymbolAddress((void**)&wproj_ptr, g_wproj);

  // (0) tf32-round GEMM inputs
  {
    int n4 = kM * kDim / 4;
    tf32_round_kernel<<<(n4 + 255) / 256, 256>>>(x, x_ptr, n4);
    n4 = kQkvN * kDim / 4;
    tf32_round_kernel<<<(n4 + 255) / 256, 256>>>(qkv_w, wqkv_ptr, n4);
    n4 = kDim * kDim / 4;
    tf32_round_kernel<<<(n4 + 255) / 256, 256>>>(proj_w, wproj_ptr, n4);
  }

  // (1) relative position bias expansion
  rpb_expand<<<(kTok * kTok + 255) / 256, 256>>>(rel_idx, rpb_table);

  // (2) QKV projection (epilogue rounds to tf32)
  cudaFuncSetAttribute(gemm_tf32_pipe<0>, cudaFuncAttributeMaxDynamicSharedMemorySize,
                       kGemmSmemBytes);
  {
    dim3 grid(kQkvN / 128, (kM + 127) / 128);
    gemm_tf32_pipe<0><<<grid, 256, kGemmSmemBytes>>>(x_ptr, wqkv_ptr, qkv_ptr,
                                                     kM, kDim, kQkvN, q_bias, v_bias);
  }

  // (3) tensor-core attention
  cudaFuncSetAttribute(attn_kernel, cudaFuncAttributeMaxDynamicSharedMemorySize,
                       kAttnSmemBytes);
  attn_kernel<<<dim3(7, kBatch * kHeads), 256, kAttnSmemBytes>>>();

  // (4) output projection
  cudaFuncSetAttribute(gemm_tf32_pipe<1>, cudaFuncAttributeMaxDynamicSharedMemorySize,
                       kGemmSmemBytes);
  {
    dim3 grid(kDim / 128, (kM + 127) / 128);
    gemm_tf32_pipe<1><<<grid, 256, kGemmSmemBytes>>>(attn_ptr, wproj_ptr, out,
                                                     kM, kDim, kDim, proj_b, nullptr);
  }
}